// round 13
// baseline (speedup 1.0000x reference)
#include <cuda_runtime.h>
#include <cuda_bf16.h>
#include <cstdint>

#define BB  8
#define CC  512
#define HWD 1024
#define RR  8192   // BB*HWD

// Scratch (device globals — no runtime allocation allowed)
__device__ __nv_bfloat16 g_xf[RR * CC];   // x transposed, bf16 [row][C]
__device__ __nv_bfloat16 g_wqb[CC * CC];  // Wq bf16
__device__ __nv_bfloat16 g_wkb[CC * CC];  // Wk bf16
__device__ __nv_bfloat16 g_q[RR * CC];    // bf16 projections
__device__ __nv_bfloat16 g_k[RR * CC];
__device__ unsigned int g_pmaxu[RR * BB]; // per-query, per-image max (orderable uint)
__device__ float g_w[BB * HWD];           // softmax gate weights

// ============================================================================
// Helpers
// ============================================================================
__device__ __forceinline__ uint32_t smem_u32(const void* p) {
    uint32_t a;
    asm("{ .reg .u64 t; cvta.to.shared.u64 t, %1; cvt.u32.u64 %0, t; }"
        : "=r"(a) : "l"(p));
    return a;
}
__device__ __forceinline__ void cp_cg16(uint32_t s, const void* g) {
    asm volatile("cp.async.cg.shared.global [%0], [%1], 16;" :: "r"(s), "l"(g));
}
__device__ __forceinline__ void cp_commit() {
    asm volatile("cp.async.commit_group;" ::: "memory");
}
template <int N> __device__ __forceinline__ void cp_wait() {
    asm volatile("cp.async.wait_group %0;" :: "n"(N) : "memory");
}
__device__ __forceinline__ void mma_tf32_16n8k8(
    float* c, uint32_t a0, uint32_t a1, uint32_t a2, uint32_t a3,
    uint32_t b0, uint32_t b1)
{
    asm volatile(
        "mma.sync.aligned.m16n8k8.row.col.f32.tf32.tf32.f32 "
        "{%0,%1,%2,%3}, {%4,%5,%6,%7}, {%8,%9}, {%0,%1,%2,%3};"
        : "+f"(c[0]), "+f"(c[1]), "+f"(c[2]), "+f"(c[3])
        : "r"(a0), "r"(a1), "r"(a2), "r"(a3), "r"(b0), "r"(b1));
}
__device__ __forceinline__ void mma_bf16_16n8k16(
    float* c, const uint32_t* a, uint32_t b0, uint32_t b1)
{
    asm volatile(
        "mma.sync.aligned.m16n8k16.row.col.f32.bf16.bf16.f32 "
        "{%0,%1,%2,%3}, {%4,%5,%6,%7}, {%8,%9}, {%0,%1,%2,%3};"
        : "+f"(c[0]), "+f"(c[1]), "+f"(c[2]), "+f"(c[3])
        : "r"(a[0]), "r"(a[1]), "r"(a[2]), "r"(a[3]), "r"(b0), "r"(b1));
}
__device__ __forceinline__ void ldm_x4(uint32_t* r, uint32_t addr) {
    asm volatile("ldmatrix.sync.aligned.m8n8.x4.shared.b16 {%0,%1,%2,%3}, [%4];"
        : "=r"(r[0]), "=r"(r[1]), "=r"(r[2]), "=r"(r[3]) : "r"(addr));
}
__device__ __forceinline__ void tf32_split(float v, uint32_t& hi, uint32_t& lo) {
    uint32_t hb = __float_as_uint(v) & 0xFFFFE000u;
    hi = hb;
    lo = __float_as_uint(v - __uint_as_float(hb));
}
// Orderable encoding: float -> uint preserving order under unsigned compare.
__device__ __forceinline__ unsigned int fenc(float f) {
    unsigned int u = __float_as_uint(f);
    return (u & 0x80000000u) ? ~u : (u | 0x80000000u);
}
__device__ __forceinline__ float fdec(unsigned int u) {
    return __uint_as_float((u & 0x80000000u) ? (u & 0x7FFFFFFFu) : ~u);
}

// Shared tiling constants
#define SBK  32      // K-chunk
#define PADR 36      // fp32 [rows][k] pad (outconv)
#define PADK 136     // fp32 [k][cols] pad (outconv)
#define PB 40        // bf16 elems per smem row (32 + 8 pad)

// bf16 GEMM smem (4-stage ring)
#define SC_TILE_B (128 * PB * 2)      // 10240 bytes (A or B tile)
#define SC_STAGE_B (2 * SC_TILE_B)    // 20480
#define SC_RED_OFF (4 * SC_STAGE_B)   // 81920
#define SC_SMEM (SC_RED_OFF + 512 * 4)

// ============================================================================
// Kernel A: x transpose to bf16 [row][C] + g_pmaxu init.
//   grid (32, 16, 8), 256 threads.
// ============================================================================
__global__ __launch_bounds__(256) void xpose_kernel(const float* __restrict__ x)
{
    __shared__ float tile[32][33];
    const int p0 = blockIdx.x * 32;
    const int c0 = blockIdx.y * 32;
    const int b  = blockIdx.z;
    const int t  = threadIdx.x;
    const int tj = t & 31, ti = t >> 5;

    if (blockIdx.y == 0) {
        int lin = (blockIdx.z * 32 + blockIdx.x) * 256 + t;   // 0..65535
        g_pmaxu[lin] = fenc(-1e30f);
    }

    #pragma unroll
    for (int rr = 0; rr < 4; rr++) {
        int i = rr * 8 + ti;
        tile[i][tj] = x[((size_t)b * CC + c0 + i) * HWD + p0 + tj];
    }
    __syncthreads();
    #pragma unroll
    for (int rr = 0; rr < 4; rr++) {
        int pi = rr * 8 + ti;
        g_xf[((size_t)b * HWD + p0 + pi) * CC + c0 + tj] =
            __float2bfloat16(tile[tj][pi]);
    }
}

// ============================================================================
// Kernel B: Wq/Wk -> bf16.  grid (512, 2), 256 threads.
// ============================================================================
__global__ __launch_bounds__(256) void wconv_kernel(
    const float* __restrict__ Wq, const float* __restrict__ Wk)
{
    const int row = blockIdx.x;
    const int dst = blockIdx.y;
    const float* W = dst ? Wk : Wq;
    __nv_bfloat16* O = dst ? g_wkb : g_wqb;
    const int t = threadIdx.x;
    #pragma unroll
    for (int u = 0; u < 2; u++) {
        int j = t + u * 256;
        O[(size_t)row * CC + j] = __float2bfloat16(W[(size_t)row * CC + j]);
    }
}

// ============================================================================
// Kernel 1: q/k projection on bf16 mma (m16n8k16) + ldmatrix, 4-stage ring.
//   grid (64, 4, 2). Block: 128 rows (g_xf) x 128 co (W bf16), K=512.
// ============================================================================
__global__ __launch_bounds__(256, 2) void projb_kernel(
    const float* __restrict__ bq, const float* __restrict__ bk)
{
    extern __shared__ char smc[];
    const uint32_t sbase = smem_u32(smc);

    const int t    = threadIdx.x;
    const int lane = t & 31;
    const int wid  = t >> 5;
    const int wm   = wid >> 2;
    const int wn   = wid & 3;
    const int gid  = lane >> 2;
    const int tig  = lane & 3;
    const int lrow = lane & 15;
    const int lseg = (lane >> 4) * 8;

    const int dst = blockIdx.z;
    const int r0  = blockIdx.x * 128;
    const int co0 = blockIdx.y * 128;
    const __nv_bfloat16* Ap = g_xf + (size_t)r0 * CC;
    const __nv_bfloat16* Bp = (dst ? g_wkb : g_wqb) + (size_t)co0 * CC;
    const float* bias = dst ? bk : bq;
    __nv_bfloat16* out = dst ? g_k : g_q;

    auto issue = [&](int c) {
        const int s  = c & 3;
        const int k0 = c * SBK;
        uint32_t As = sbase + (uint32_t)(s * SC_STAGE_B);
        #pragma unroll
        for (int u = 0; u < 2; u++) {
            int f = t + u * 256, r = f & 127, seg = f >> 7;
            cp_cg16(As + (uint32_t)(r * PB + seg * 8) * 2,
                    Ap + (size_t)r * CC + k0 + seg * 8);
        }
        uint32_t Bs = As + SC_TILE_B;
        #pragma unroll
        for (int u = 0; u < 2; u++) {
            int f = t + u * 256, r = f & 127, seg = f >> 7;
            cp_cg16(Bs + (uint32_t)(r * PB + seg * 8) * 2,
                    Bp + (size_t)r * CC + k0 + seg * 8);
        }
        cp_commit();
    };

    float acc[4][4][4];
    #pragma unroll
    for (int mt = 0; mt < 4; mt++)
        #pragma unroll
        for (int nt = 0; nt < 4; nt++)
            #pragma unroll
            for (int v = 0; v < 4; v++) acc[mt][nt][v] = 0.f;

    issue(0); issue(1); issue(2);
    for (int c = 0; c < 16; ++c) {
        if (c < 14) cp_wait<2>();
        else if (c == 14) cp_wait<1>();
        else cp_wait<0>();
        __syncthreads();
        if (c + 3 < 16) issue(c + 3);

        const uint32_t Ab = sbase + (uint32_t)((c & 3) * SC_STAGE_B);
        const uint32_t Bb = Ab + SC_TILE_B;

        #pragma unroll
        for (int ks = 0; ks < 2; ++ks) {
            const int kcol = ks * 16 + lseg;
            uint32_t a[4][4];
            #pragma unroll
            for (int mt = 0; mt < 4; ++mt)
                ldm_x4(a[mt], Ab + (uint32_t)((wm * 64 + mt * 16 + lrow) * PB + kcol) * 2);
            uint32_t bf[2][4];
            #pragma unroll
            for (int nh = 0; nh < 2; ++nh)
                ldm_x4(bf[nh], Bb + (uint32_t)((wn * 32 + nh * 16 + lrow) * PB + kcol) * 2);
            #pragma unroll
            for (int nt = 0; nt < 4; ++nt) {
                uint32_t b0 = bf[nt >> 1][nt & 1];
                uint32_t b1 = bf[nt >> 1][(nt & 1) + 2];
                #pragma unroll
                for (int mt = 0; mt < 4; ++mt)
                    mma_bf16_16n8k16(acc[mt][nt], a[mt], b0, b1);
            }
        }
    }

    #pragma unroll
    for (int mt = 0; mt < 4; ++mt) {
        int row = r0 + wm * 64 + mt * 16 + gid;
        #pragma unroll
        for (int nt = 0; nt < 4; ++nt) {
            int co = co0 + wn * 32 + nt * 8 + tig * 2;
            float bs0 = bias[co], bs1 = bias[co + 1];
            __nv_bfloat162 v0, v1;
            v0.x = __float2bfloat16(acc[mt][nt][0] + bs0);
            v0.y = __float2bfloat16(acc[mt][nt][1] + bs1);
            v1.x = __float2bfloat16(acc[mt][nt][2] + bs0);
            v1.y = __float2bfloat16(acc[mt][nt][3] + bs1);
            *(__nv_bfloat162*)&out[(size_t)row * CC + co]       = v0;
            *(__nv_bfloat162*)&out[(size_t)(row + 8) * CC + co] = v1;
        }
    }
}

// ============================================================================
// Kernel 2: PERSISTENT fused scores + per-image max (bf16 mma + ldmatrix).
//   grid = 304 blocks (2/SM), each streams ~13-14 items of
//   (qt, img, nt) = 128 q x 128 keys x K512 = 16 K-chunks through one
//   continuous 4-stage cp.async ring (no drain at item boundaries).
// ============================================================================
#define N_ITEMS 4096                  // 64 qt x 8 img x 8 nt
#define GRID_SC 304

__global__ __launch_bounds__(256, 2) void scores_mma_kernel()
{
    extern __shared__ char smc[];
    const uint32_t sbase = smem_u32(smc);

    const int t    = threadIdx.x;
    const int lane = t & 31;
    const int wid  = t >> 5;
    const int wm   = wid >> 2;
    const int wn   = wid & 3;
    const int gid  = lane >> 2;
    const int tig  = lane & 3;
    const int blk  = blockIdx.x;

    const int n_items  = (N_ITEMS - blk + GRID_SC - 1) / GRID_SC;
    const int n_chunks = n_items * 16;

    float* red = (float*)(smc + SC_RED_OFF);

    const int lrow = lane & 15;
    const int lseg = (lane >> 4) * 8;

    auto issue = [&](int gc) {
        const int it  = blk + (gc >> 4) * GRID_SC;
        const int k0  = (gc & 15) * SBK;
        const int s   = gc & 3;
        const __nv_bfloat16* qp = g_q + (size_t)(it >> 6) * 128 * CC;
        const __nv_bfloat16* kp = g_k +
            (size_t)((((it >> 3) & 7) * HWD) + (it & 7) * 128) * CC;
        uint32_t As = sbase + (uint32_t)(s * SC_STAGE_B);
        #pragma unroll
        for (int u = 0; u < 2; u++) {
            int f = t + u * 256, r = f & 127, seg = f >> 7;
            cp_cg16(As + (uint32_t)(r * PB + seg * 8) * 2,
                    qp + (size_t)r * CC + k0 + seg * 8);
        }
        uint32_t Bs = As + SC_TILE_B;
        #pragma unroll
        for (int u = 0; u < 2; u++) {
            int f = t + u * 256, r = f & 127, seg = f >> 7;
            cp_cg16(Bs + (uint32_t)(r * PB + seg * 8) * 2,
                    kp + (size_t)r * CC + k0 + seg * 8);
        }
        cp_commit();
    };

    float acc[4][4][4];

    issue(0); issue(1); issue(2);
    for (int gc = 0; gc < n_chunks; ++gc) {
        if ((gc & 15) == 0) {
            #pragma unroll
            for (int mt = 0; mt < 4; mt++)
                #pragma unroll
                for (int nt = 0; nt < 4; nt++)
                    #pragma unroll
                    for (int v = 0; v < 4; v++) acc[mt][nt][v] = 0.f;
        }
        if (gc < n_chunks - 2) cp_wait<2>();
        else if (gc == n_chunks - 2) cp_wait<1>();
        else cp_wait<0>();
        __syncthreads();
        if (gc + 3 < n_chunks) issue(gc + 3);

        const uint32_t Ab = sbase + (uint32_t)((gc & 3) * SC_STAGE_B);
        const uint32_t Bb = Ab + SC_TILE_B;

        #pragma unroll
        for (int ks = 0; ks < 2; ++ks) {
            const int kcol = ks * 16 + lseg;
            uint32_t a[4][4];
            #pragma unroll
            for (int mt = 0; mt < 4; ++mt)
                ldm_x4(a[mt], Ab + (uint32_t)((wm * 64 + mt * 16 + lrow) * PB + kcol) * 2);
            uint32_t bf[2][4];
            #pragma unroll
            for (int nh = 0; nh < 2; ++nh)
                ldm_x4(bf[nh], Bb + (uint32_t)((wn * 32 + nh * 16 + lrow) * PB + kcol) * 2);
            #pragma unroll
            for (int nt = 0; nt < 4; ++nt) {
                uint32_t b0 = bf[nt >> 1][nt & 1];
                uint32_t b1 = bf[nt >> 1][(nt & 1) + 2];
                #pragma unroll
                for (int mt = 0; mt < 4; ++mt)
                    mma_bf16_16n8k16(acc[mt][nt], a[mt], b0, b1);
            }
        }

        if ((gc & 15) == 15) {
            #pragma unroll
            for (int mt = 0; mt < 4; ++mt) {
                float m0 = -1e30f, m1 = -1e30f;
                #pragma unroll
                for (int nt = 0; nt < 4; ++nt) {
                    m0 = fmaxf(m0, fmaxf(acc[mt][nt][0], acc[mt][nt][1]));
                    m1 = fmaxf(m1, fmaxf(acc[mt][nt][2], acc[mt][nt][3]));
                }
                m0 = fmaxf(m0, __shfl_xor_sync(0xffffffffu, m0, 1));
                m0 = fmaxf(m0, __shfl_xor_sync(0xffffffffu, m0, 2));
                m1 = fmaxf(m1, __shfl_xor_sync(0xffffffffu, m1, 1));
                m1 = fmaxf(m1, __shfl_xor_sync(0xffffffffu, m1, 2));
                if (tig == 0) {
                    int r = wm * 64 + mt * 16 + gid;
                    red[wn * 128 + r]     = m0;
                    red[wn * 128 + r + 8] = m1;
                }
            }
            __syncthreads();
            if (t < 128) {
                float v = fmaxf(fmaxf(red[t], red[128 + t]),
                                fmaxf(red[256 + t], red[384 + t]));
                int it  = blk + (gc >> 4) * GRID_SC;
                int qt  = it >> 6;
                int img = (it >> 3) & 7;
                atomicMax(&g_pmaxu[(size_t)(qt * 128 + t) * BB + img], fenc(v));
            }
            __syncthreads();
        }
    }
}

// ============================================================================
// Kernel 3: logits = mean-over-images(pmax) / sqrt(C); softmax per batch.
// ============================================================================
__global__ __launch_bounds__(256) void softmax_kernel()
{
    const int b = blockIdx.x;
    const int t = threadIdx.x;
    __shared__ float smr[256];
    __shared__ float logits[HWD];
    const float scale = 1.0f / sqrtf((float)CC);

    float lmax = -1e30f;
    for (int p = t; p < HWD; p += 256) {
        float s = 0.f;
        #pragma unroll
        for (int img = 0; img < BB; img++)
            s += fdec(g_pmaxu[(size_t)(b * HWD + p) * BB + img]);
        float lg = s * (1.0f / BB) * scale;
        logits[p] = lg;
        lmax = fmaxf(lmax, lg);
    }
    smr[t] = lmax; __syncthreads();
    for (int s = 128; s > 0; s >>= 1) {
        if (t < s) smr[t] = fmaxf(smr[t], smr[t + s]);
        __syncthreads();
    }
    float gmax = smr[0]; __syncthreads();

    float lsum = 0.f;
    for (int p = t; p < HWD; p += 256) {
        float e = expf(logits[p] - gmax);
        logits[p] = e;
        lsum += e;
    }
    smr[t] = lsum; __syncthreads();
    for (int s = 128; s > 0; s >>= 1) {
        if (t < s) smr[t] += smr[t + s];
        __syncthreads();
    }
    float inv = 1.0f / smr[0];
    for (int p = t; p < HWD; p += 256)
        g_w[b * HWD + p] = logits[p] * inv;
}

// ============================================================================
// Kernel 4: gated output conv, 2-term tf32 split (Ahi.Bhi + Ahi.Blo).
//   grid (4, 8, 8). 2 CTAs/SM.
// ============================================================================
#define PJ_A_F (SBK * PADK)
#define PJ_B_F (128 * PADR)
#define PJ_SMEM (3 * (PJ_A_F + PJ_B_F) * 4)

__global__ __launch_bounds__(256, 2) void outconv_tc_kernel(
    const float* __restrict__ x, const float* __restrict__ W6,
    const float* __restrict__ b6, float* __restrict__ out)
{
    extern __shared__ float sm[];
    const uint32_t sbase = smem_u32(sm);

    const int t    = threadIdx.x;
    const int lane = t & 31;
    const int wid  = t >> 5;
    const int wm   = wid >> 2;
    const int wn   = wid & 3;
    const int gid  = lane >> 2;
    const int tig  = lane & 3;

    const int co0 = blockIdx.x * 128;
    const int p0  = blockIdx.y * 128;
    const int b   = blockIdx.z;
    const float* xb = x + (size_t)b * CC * HWD;

    auto issue = [&](int c) {
        const int s  = c % 3;
        const int k0 = c * SBK;
        uint32_t As = sbase + (uint32_t)(s * PJ_B_F) * 4;      // [co][k] PADR
        #pragma unroll
        for (int u = 0; u < 4; u++) {
            int f = t + u * 256, m = f >> 3, c4 = (f & 7) * 4;
            cp_cg16(As + (uint32_t)(m * PADR + c4) * 4,
                    W6 + (size_t)(co0 + m) * CC + k0 + c4);
        }
        uint32_t Bs = sbase + (uint32_t)(3 * PJ_B_F + s * PJ_A_F) * 4;  // [k][p] PADK
        #pragma unroll
        for (int u = 0; u < 4; u++) {
            int f = t + u * 256, kk = f >> 5, p4 = (f & 31) * 4;
            cp_cg16(Bs + (uint32_t)(kk * PADK + p4) * 4,
                    xb + (size_t)(k0 + kk) * HWD + p0 + p4);
        }
        cp_commit();
    };

    float acc[4][4][4];
    #pragma unroll
    for (int mt = 0; mt < 4; mt++)
        #pragma unroll
        for (int nt = 0; nt < 4; nt++)
            #pragma unroll
            for (int v = 0; v < 4; v++) acc[mt][nt][v] = 0.f;

    issue(0); issue(1);
    for (int c = 0; c < 16; ++c) {
        if (c < 15) cp_wait<1>(); else cp_wait<0>();
        __syncthreads();
        if (c + 2 < 16) issue(c + 2);

        const float* Ab = sm + (c % 3) * PJ_B_F;                 // [co][k]
        const float* Bb = sm + 3 * PJ_B_F + (c % 3) * PJ_A_F;    // [k][p]

        #pragma unroll
        for (int ks = 0; ks < 4; ++ks) {
            const int col = ks * 8 + tig;
            uint32_t ah[4][4];
            #pragma unroll
            for (int mt = 0; mt < 4; ++mt) {
                int m = wm * 64 + mt * 16 + gid;
                ah[mt][0] = __float_as_uint(Ab[m * PADR + col])           & 0xFFFFE000u;
                ah[mt][1] = __float_as_uint(Ab[(m + 8) * PADR + col])     & 0xFFFFE000u;
                ah[mt][2] = __float_as_uint(Ab[m * PADR + col + 4])       & 0xFFFFE000u;
                ah[mt][3] = __float_as_uint(Ab[(m + 8) * PADR + col + 4]) & 0xFFFFE000u;
            }
            #pragma unroll
            for (int nt = 0; nt < 4; ++nt) {
                int n = wn * 32 + nt * 8 + gid;
                uint32_t bh0, bl0, bh1, bl1;
                tf32_split(Bb[col * PADK + n],       bh0, bl0);
                tf32_split(Bb[(col + 4) * PADK + n], bh1, bl1);
                #pragma unroll
                for (int mt = 0; mt < 4; ++mt) {
                    mma_tf32_16n8k8(acc[mt][nt],
                                    ah[mt][0], ah[mt][1], ah[mt][2], ah[mt][3],
                                    bh0, bh1);
                    mma_tf32_16n8k8(acc[mt][nt],
                                    ah[mt][0], ah[mt][1], ah[mt][2], ah[mt][3],
                                    bl0, bl1);
                }
            }
        }
    }

    #pragma unroll
    for (int mt = 0; mt < 4; ++mt) {
        int co = co0 + wm * 64 + mt * 16 + gid;
        float bs0 = b6[co], bs1 = b6[co + 8];
        #pragma unroll
        for (int nt = 0; nt < 4; ++nt) {
            int p = p0 + wn * 32 + nt * 8 + tig * 2;
            float g0 = g_w[b * HWD + p];
            float g1 = g_w[b * HWD + p + 1];
            float2 o0 = { acc[mt][nt][0] * g0 + bs0, acc[mt][nt][1] * g1 + bs0 };
            float2 o1 = { acc[mt][nt][2] * g0 + bs1, acc[mt][nt][3] * g1 + bs1 };
            *(float2*)&out[((size_t)(b * CC + co)) * HWD + p]     = o0;
            *(float2*)&out[((size_t)(b * CC + co + 8)) * HWD + p] = o1;
        }
    }
}

// ============================================================================
extern "C" void kernel_launch(void* const* d_in, const int* in_sizes, int n_in,
                              void* d_out, int out_size)
{
    const float* x  = (const float*)d_in[0];
    const float* Wq = (const float*)d_in[1];
    const float* bq = (const float*)d_in[2];
    const float* Wk = (const float*)d_in[3];
    const float* bk = (const float*)d_in[4];
    const float* W6 = (const float*)d_in[5];
    const float* b6 = (const float*)d_in[6];
    float* out = (float*)d_out;

    cudaFuncSetAttribute(projb_kernel,
                         cudaFuncAttributeMaxDynamicSharedMemorySize, SC_SMEM);
    cudaFuncSetAttribute(scores_mma_kernel,
                         cudaFuncAttributeMaxDynamicSharedMemorySize, SC_SMEM);
    cudaFuncSetAttribute(outconv_tc_kernel,
                         cudaFuncAttributeMaxDynamicSharedMemorySize, PJ_SMEM);

    dim3 blk(256);
    wconv_kernel<<<dim3(512, 2), blk>>>(Wq, Wk);
    xpose_kernel<<<dim3(32, 16, 8), blk>>>(x);
    projb_kernel<<<dim3(64, 4, 2), blk, SC_SMEM>>>(bq, bk);
    scores_mma_kernel<<<GRID_SC, blk, SC_SMEM>>>();
    softmax_kernel<<<BB, blk>>>();
    outconv_tc_kernel<<<dim3(CC / 128, HWD / 128, BB), blk, PJ_SMEM>>>(x, W6, b6, out);
}

// round 14
// speedup vs baseline: 1.0106x; 1.0106x over previous
#include <cuda_runtime.h>
#include <cuda_bf16.h>
#include <cstdint>

#define BB  8
#define CC  512
#define HWD 1024
#define RR  8192   // BB*HWD

// Scratch (device globals — no runtime allocation allowed)
__device__ __nv_bfloat16 g_xf[RR * CC];   // x transposed, bf16 [row][C]
__device__ __nv_bfloat16 g_wqb[CC * CC];  // Wq bf16
__device__ __nv_bfloat16 g_wkb[CC * CC];  // Wk bf16
__device__ __nv_bfloat16 g_q[RR * CC];    // bf16 projections
__device__ __nv_bfloat16 g_k[RR * CC];
__device__ unsigned int g_pmaxu[RR * BB]; // per-query, per-image max (orderable uint)
__device__ float g_w[BB * HWD];           // softmax gate weights

// ============================================================================
// Helpers
// ============================================================================
__device__ __forceinline__ uint32_t smem_u32(const void* p) {
    uint32_t a;
    asm("{ .reg .u64 t; cvta.to.shared.u64 t, %1; cvt.u32.u64 %0, t; }"
        : "=r"(a) : "l"(p));
    return a;
}
__device__ __forceinline__ void cp_cg16(uint32_t s, const void* g) {
    asm volatile("cp.async.cg.shared.global [%0], [%1], 16;" :: "r"(s), "l"(g));
}
__device__ __forceinline__ void cp_commit() {
    asm volatile("cp.async.commit_group;" ::: "memory");
}
template <int N> __device__ __forceinline__ void cp_wait() {
    asm volatile("cp.async.wait_group %0;" :: "n"(N) : "memory");
}
__device__ __forceinline__ void mma_tf32_16n8k8(
    float* c, uint32_t a0, uint32_t a1, uint32_t a2, uint32_t a3,
    uint32_t b0, uint32_t b1)
{
    asm volatile(
        "mma.sync.aligned.m16n8k8.row.col.f32.tf32.tf32.f32 "
        "{%0,%1,%2,%3}, {%4,%5,%6,%7}, {%8,%9}, {%0,%1,%2,%3};"
        : "+f"(c[0]), "+f"(c[1]), "+f"(c[2]), "+f"(c[3])
        : "r"(a0), "r"(a1), "r"(a2), "r"(a3), "r"(b0), "r"(b1));
}
__device__ __forceinline__ void mma_bf16_16n8k16(
    float* c, const uint32_t* a, uint32_t b0, uint32_t b1)
{
    asm volatile(
        "mma.sync.aligned.m16n8k16.row.col.f32.bf16.bf16.f32 "
        "{%0,%1,%2,%3}, {%4,%5,%6,%7}, {%8,%9}, {%0,%1,%2,%3};"
        : "+f"(c[0]), "+f"(c[1]), "+f"(c[2]), "+f"(c[3])
        : "r"(a[0]), "r"(a[1]), "r"(a[2]), "r"(a[3]), "r"(b0), "r"(b1));
}
__device__ __forceinline__ void ldm_x4(uint32_t* r, uint32_t addr) {
    asm volatile("ldmatrix.sync.aligned.m8n8.x4.shared.b16 {%0,%1,%2,%3}, [%4];"
        : "=r"(r[0]), "=r"(r[1]), "=r"(r[2]), "=r"(r[3]) : "r"(addr));
}
__device__ __forceinline__ void tf32_split(float v, uint32_t& hi, uint32_t& lo) {
    uint32_t hb = __float_as_uint(v) & 0xFFFFE000u;
    hi = hb;
    lo = __float_as_uint(v - __uint_as_float(hb));
}
// Orderable encoding: float -> uint preserving order under unsigned compare.
__device__ __forceinline__ unsigned int fenc(float f) {
    unsigned int u = __float_as_uint(f);
    return (u & 0x80000000u) ? ~u : (u | 0x80000000u);
}
__device__ __forceinline__ float fdec(unsigned int u) {
    return __uint_as_float((u & 0x80000000u) ? (u & 0x7FFFFFFFu) : ~u);
}

// Shared tiling constants
#define SBK  32      // K-chunk
#define PADR 36      // fp32 [rows][k] pad (outconv)
#define PADK 136     // fp32 [k][cols] pad (outconv)
#define PB 40        // bf16 elems per smem row (32 + 8 pad)

// bf16 GEMM smem tiles
#define SC_TILE_B (128 * PB * 2)      // 10240 bytes (A or B tile)
#define SC_STAGE_B (2 * SC_TILE_B)    // 20480
// projb: 4-stage ring
#define PJ4_RED_OFF (4 * SC_STAGE_B)  // 81920
#define PJ4_SMEM (PJ4_RED_OFF + 512 * 4)
// scores: 3-stage ring (R12 proven)
#define SC3_RED_OFF (3 * SC_STAGE_B)  // 61440
#define SC3_SMEM (SC3_RED_OFF + 512 * 4)

// ============================================================================
// Kernel A: x transpose to bf16 [row][C] + g_pmaxu init.
//   grid (32, 16, 8), 256 threads.
// ============================================================================
__global__ __launch_bounds__(256) void xpose_kernel(const float* __restrict__ x)
{
    __shared__ float tile[32][33];
    const int p0 = blockIdx.x * 32;
    const int c0 = blockIdx.y * 32;
    const int b  = blockIdx.z;
    const int t  = threadIdx.x;
    const int tj = t & 31, ti = t >> 5;

    if (blockIdx.y == 0) {
        int lin = (blockIdx.z * 32 + blockIdx.x) * 256 + t;   // 0..65535
        g_pmaxu[lin] = fenc(-1e30f);
    }

    #pragma unroll
    for (int rr = 0; rr < 4; rr++) {
        int i = rr * 8 + ti;
        tile[i][tj] = x[((size_t)b * CC + c0 + i) * HWD + p0 + tj];
    }
    __syncthreads();
    #pragma unroll
    for (int rr = 0; rr < 4; rr++) {
        int pi = rr * 8 + ti;
        g_xf[((size_t)b * HWD + p0 + pi) * CC + c0 + tj] =
            __float2bfloat16(tile[tj][pi]);
    }
}

// ============================================================================
// Kernel B: Wq/Wk -> bf16.  grid (512, 2), 256 threads.
// ============================================================================
__global__ __launch_bounds__(256) void wconv_kernel(
    const float* __restrict__ Wq, const float* __restrict__ Wk)
{
    const int row = blockIdx.x;
    const int dst = blockIdx.y;
    const float* W = dst ? Wk : Wq;
    __nv_bfloat16* O = dst ? g_wkb : g_wqb;
    const int t = threadIdx.x;
    #pragma unroll
    for (int u = 0; u < 2; u++) {
        int j = t + u * 256;
        O[(size_t)row * CC + j] = __float2bfloat16(W[(size_t)row * CC + j]);
    }
}

// ============================================================================
// Kernel 1: q/k projection on bf16 mma (m16n8k16) + ldmatrix, 4-stage ring.
//   grid (64, 4, 2). Block: 128 rows (g_xf) x 128 co (W bf16), K=512.
// ============================================================================
__global__ __launch_bounds__(256, 2) void projb_kernel(
    const float* __restrict__ bq, const float* __restrict__ bk)
{
    extern __shared__ char smc[];
    const uint32_t sbase = smem_u32(smc);

    const int t    = threadIdx.x;
    const int lane = t & 31;
    const int wid  = t >> 5;
    const int wm   = wid >> 2;
    const int wn   = wid & 3;
    const int gid  = lane >> 2;
    const int tig  = lane & 3;
    const int lrow = lane & 15;
    const int lseg = (lane >> 4) * 8;

    const int dst = blockIdx.z;
    const int r0  = blockIdx.x * 128;
    const int co0 = blockIdx.y * 128;
    const __nv_bfloat16* Ap = g_xf + (size_t)r0 * CC;
    const __nv_bfloat16* Bp = (dst ? g_wkb : g_wqb) + (size_t)co0 * CC;
    const float* bias = dst ? bk : bq;
    __nv_bfloat16* out = dst ? g_k : g_q;

    auto issue = [&](int c) {
        const int s  = c & 3;
        const int k0 = c * SBK;
        uint32_t As = sbase + (uint32_t)(s * SC_STAGE_B);
        #pragma unroll
        for (int u = 0; u < 2; u++) {
            int f = t + u * 256, r = f & 127, seg = f >> 7;
            cp_cg16(As + (uint32_t)(r * PB + seg * 8) * 2,
                    Ap + (size_t)r * CC + k0 + seg * 8);
        }
        uint32_t Bs = As + SC_TILE_B;
        #pragma unroll
        for (int u = 0; u < 2; u++) {
            int f = t + u * 256, r = f & 127, seg = f >> 7;
            cp_cg16(Bs + (uint32_t)(r * PB + seg * 8) * 2,
                    Bp + (size_t)r * CC + k0 + seg * 8);
        }
        cp_commit();
    };

    float acc[4][4][4];
    #pragma unroll
    for (int mt = 0; mt < 4; mt++)
        #pragma unroll
        for (int nt = 0; nt < 4; nt++)
            #pragma unroll
            for (int v = 0; v < 4; v++) acc[mt][nt][v] = 0.f;

    issue(0); issue(1); issue(2);
    for (int c = 0; c < 16; ++c) {
        if (c < 14) cp_wait<2>();
        else if (c == 14) cp_wait<1>();
        else cp_wait<0>();
        __syncthreads();
        if (c + 3 < 16) issue(c + 3);

        const uint32_t Ab = sbase + (uint32_t)((c & 3) * SC_STAGE_B);
        const uint32_t Bb = Ab + SC_TILE_B;

        #pragma unroll
        for (int ks = 0; ks < 2; ++ks) {
            const int kcol = ks * 16 + lseg;
            uint32_t a[4][4];
            #pragma unroll
            for (int mt = 0; mt < 4; ++mt)
                ldm_x4(a[mt], Ab + (uint32_t)((wm * 64 + mt * 16 + lrow) * PB + kcol) * 2);
            uint32_t bf[2][4];
            #pragma unroll
            for (int nh = 0; nh < 2; ++nh)
                ldm_x4(bf[nh], Bb + (uint32_t)((wn * 32 + nh * 16 + lrow) * PB + kcol) * 2);
            #pragma unroll
            for (int nt = 0; nt < 4; ++nt) {
                uint32_t b0 = bf[nt >> 1][nt & 1];
                uint32_t b1 = bf[nt >> 1][(nt & 1) + 2];
                #pragma unroll
                for (int mt = 0; mt < 4; ++mt)
                    mma_bf16_16n8k16(acc[mt][nt], a[mt], b0, b1);
            }
        }
    }

    #pragma unroll
    for (int mt = 0; mt < 4; ++mt) {
        int row = r0 + wm * 64 + mt * 16 + gid;
        #pragma unroll
        for (int nt = 0; nt < 4; ++nt) {
            int co = co0 + wn * 32 + nt * 8 + tig * 2;
            float bs0 = bias[co], bs1 = bias[co + 1];
            __nv_bfloat162 v0, v1;
            v0.x = __float2bfloat16(acc[mt][nt][0] + bs0);
            v0.y = __float2bfloat16(acc[mt][nt][1] + bs1);
            v1.x = __float2bfloat16(acc[mt][nt][2] + bs0);
            v1.y = __float2bfloat16(acc[mt][nt][3] + bs1);
            *(__nv_bfloat162*)&out[(size_t)row * CC + co]       = v0;
            *(__nv_bfloat162*)&out[(size_t)(row + 8) * CC + co] = v1;
        }
    }
}

// ============================================================================
// Kernel 2: PERSISTENT fused scores + per-image max (bf16 mma + ldmatrix).
//   R12-proven version: 3-stage cp.async ring, cp_wait<1>.
//   grid = 304 blocks (2/SM), each streams ~13-14 items of
//   (qt, img, nt) = 128 q x 128 keys x K512 = 16 K-chunks.
// ============================================================================
#define N_ITEMS 4096                  // 64 qt x 8 img x 8 nt
#define GRID_SC 304

__global__ __launch_bounds__(256, 2) void scores_mma_kernel()
{
    extern __shared__ char smc[];
    const uint32_t sbase = smem_u32(smc);

    const int t    = threadIdx.x;
    const int lane = t & 31;
    const int wid  = t >> 5;
    const int wm   = wid >> 2;
    const int wn   = wid & 3;
    const int gid  = lane >> 2;
    const int tig  = lane & 3;
    const int blk  = blockIdx.x;

    const int n_items  = (N_ITEMS - blk + GRID_SC - 1) / GRID_SC;
    const int n_chunks = n_items * 16;

    float* red = (float*)(smc + SC3_RED_OFF);

    const int lrow = lane & 15;
    const int lseg = (lane >> 4) * 8;

    auto issue = [&](int gc) {
        const int it  = blk + (gc >> 4) * GRID_SC;
        const int k0  = (gc & 15) * SBK;
        const int s   = gc % 3;
        const __nv_bfloat16* qp = g_q + (size_t)(it >> 6) * 128 * CC;
        const __nv_bfloat16* kp = g_k +
            (size_t)((((it >> 3) & 7) * HWD) + (it & 7) * 128) * CC;
        uint32_t As = sbase + (uint32_t)(s * SC_STAGE_B);
        #pragma unroll
        for (int u = 0; u < 2; u++) {
            int f = t + u * 256, r = f & 127, seg = f >> 7;   // conflict-free STS
            cp_cg16(As + (uint32_t)(r * PB + seg * 8) * 2,
                    qp + (size_t)r * CC + k0 + seg * 8);
        }
        uint32_t Bs = As + SC_TILE_B;
        #pragma unroll
        for (int u = 0; u < 2; u++) {
            int f = t + u * 256, r = f & 127, seg = f >> 7;
            cp_cg16(Bs + (uint32_t)(r * PB + seg * 8) * 2,
                    kp + (size_t)r * CC + k0 + seg * 8);
        }
        cp_commit();
    };

    float acc[4][4][4];

    issue(0); issue(1);
    for (int gc = 0; gc < n_chunks; ++gc) {
        if ((gc & 15) == 0) {
            #pragma unroll
            for (int mt = 0; mt < 4; mt++)
                #pragma unroll
                for (int nt = 0; nt < 4; nt++)
                    #pragma unroll
                    for (int v = 0; v < 4; v++) acc[mt][nt][v] = 0.f;
        }
        if (gc < n_chunks - 1) cp_wait<1>(); else cp_wait<0>();
        __syncthreads();
        if (gc + 2 < n_chunks) issue(gc + 2);

        const uint32_t Ab = sbase + (uint32_t)((gc % 3) * SC_STAGE_B);
        const uint32_t Bb = Ab + SC_TILE_B;

        #pragma unroll
        for (int ks = 0; ks < 2; ++ks) {
            const int kcol = ks * 16 + lseg;
            uint32_t a[4][4];
            #pragma unroll
            for (int mt = 0; mt < 4; ++mt)
                ldm_x4(a[mt], Ab + (uint32_t)((wm * 64 + mt * 16 + lrow) * PB + kcol) * 2);
            uint32_t bf[2][4];
            #pragma unroll
            for (int nh = 0; nh < 2; ++nh)
                ldm_x4(bf[nh], Bb + (uint32_t)((wn * 32 + nh * 16 + lrow) * PB + kcol) * 2);
            #pragma unroll
            for (int nt = 0; nt < 4; ++nt) {
                uint32_t b0 = bf[nt >> 1][nt & 1];
                uint32_t b1 = bf[nt >> 1][(nt & 1) + 2];
                #pragma unroll
                for (int mt = 0; mt < 4; ++mt)
                    mma_bf16_16n8k16(acc[mt][nt], a[mt], b0, b1);
            }
        }

        if ((gc & 15) == 15) {
            #pragma unroll
            for (int mt = 0; mt < 4; ++mt) {
                float m0 = -1e30f, m1 = -1e30f;
                #pragma unroll
                for (int nt = 0; nt < 4; ++nt) {
                    m0 = fmaxf(m0, fmaxf(acc[mt][nt][0], acc[mt][nt][1]));
                    m1 = fmaxf(m1, fmaxf(acc[mt][nt][2], acc[mt][nt][3]));
                }
                m0 = fmaxf(m0, __shfl_xor_sync(0xffffffffu, m0, 1));
                m0 = fmaxf(m0, __shfl_xor_sync(0xffffffffu, m0, 2));
                m1 = fmaxf(m1, __shfl_xor_sync(0xffffffffu, m1, 1));
                m1 = fmaxf(m1, __shfl_xor_sync(0xffffffffu, m1, 2));
                if (tig == 0) {
                    int r = wm * 64 + mt * 16 + gid;
                    red[wn * 128 + r]     = m0;
                    red[wn * 128 + r + 8] = m1;
                }
            }
            __syncthreads();
            if (t < 128) {
                float v = fmaxf(fmaxf(red[t], red[128 + t]),
                                fmaxf(red[256 + t], red[384 + t]));
                int it  = blk + (gc >> 4) * GRID_SC;
                int qt  = it >> 6;
                int img = (it >> 3) & 7;
                atomicMax(&g_pmaxu[(size_t)(qt * 128 + t) * BB + img], fenc(v));
            }
            __syncthreads();
        }
    }
}

// ============================================================================
// Kernel 3: logits = mean-over-images(pmax) / sqrt(C); softmax per batch.
// ============================================================================
__global__ __launch_bounds__(256) void softmax_kernel()
{
    const int b = blockIdx.x;
    const int t = threadIdx.x;
    __shared__ float smr[256];
    __shared__ float logits[HWD];
    const float scale = 1.0f / sqrtf((float)CC);

    float lmax = -1e30f;
    for (int p = t; p < HWD; p += 256) {
        float s = 0.f;
        #pragma unroll
        for (int img = 0; img < BB; img++)
            s += fdec(g_pmaxu[(size_t)(b * HWD + p) * BB + img]);
        float lg = s * (1.0f / BB) * scale;
        logits[p] = lg;
        lmax = fmaxf(lmax, lg);
    }
    smr[t] = lmax; __syncthreads();
    for (int s = 128; s > 0; s >>= 1) {
        if (t < s) smr[t] = fmaxf(smr[t], smr[t + s]);
        __syncthreads();
    }
    float gmax = smr[0]; __syncthreads();

    float lsum = 0.f;
    for (int p = t; p < HWD; p += 256) {
        float e = expf(logits[p] - gmax);
        logits[p] = e;
        lsum += e;
    }
    smr[t] = lsum; __syncthreads();
    for (int s = 128; s > 0; s >>= 1) {
        if (t < s) smr[t] += smr[t + s];
        __syncthreads();
    }
    float inv = 1.0f / smr[0];
    for (int p = t; p < HWD; p += 256)
        g_w[b * HWD + p] = logits[p] * inv;
}

// ============================================================================
// Kernel 4: gated output conv, 2-term tf32 split (Ahi.Bhi + Ahi.Blo).
//   grid (4, 8, 8). 2 CTAs/SM.
// ============================================================================
#define PJ_A_F (SBK * PADK)
#define PJ_B_F (128 * PADR)
#define PJ_SMEM (3 * (PJ_A_F + PJ_B_F) * 4)

__global__ __launch_bounds__(256, 2) void outconv_tc_kernel(
    const float* __restrict__ x, const float* __restrict__ W6,
    const float* __restrict__ b6, float* __restrict__ out)
{
    extern __shared__ float sm[];
    const uint32_t sbase = smem_u32(sm);

    const int t    = threadIdx.x;
    const int lane = t & 31;
    const int wid  = t >> 5;
    const int wm   = wid >> 2;
    const int wn   = wid & 3;
    const int gid  = lane >> 2;
    const int tig  = lane & 3;

    const int co0 = blockIdx.x * 128;
    const int p0  = blockIdx.y * 128;
    const int b   = blockIdx.z;
    const float* xb = x + (size_t)b * CC * HWD;

    auto issue = [&](int c) {
        const int s  = c % 3;
        const int k0 = c * SBK;
        uint32_t As = sbase + (uint32_t)(s * PJ_B_F) * 4;      // [co][k] PADR
        #pragma unroll
        for (int u = 0; u < 4; u++) {
            int f = t + u * 256, m = f >> 3, c4 = (f & 7) * 4;
            cp_cg16(As + (uint32_t)(m * PADR + c4) * 4,
                    W6 + (size_t)(co0 + m) * CC + k0 + c4);
        }
        uint32_t Bs = sbase + (uint32_t)(3 * PJ_B_F + s * PJ_A_F) * 4;  // [k][p] PADK
        #pragma unroll
        for (int u = 0; u < 4; u++) {
            int f = t + u * 256, kk = f >> 5, p4 = (f & 31) * 4;
            cp_cg16(Bs + (uint32_t)(kk * PADK + p4) * 4,
                    xb + (size_t)(k0 + kk) * HWD + p0 + p4);
        }
        cp_commit();
    };

    float acc[4][4][4];
    #pragma unroll
    for (int mt = 0; mt < 4; mt++)
        #pragma unroll
        for (int nt = 0; nt < 4; nt++)
            #pragma unroll
            for (int v = 0; v < 4; v++) acc[mt][nt][v] = 0.f;

    issue(0); issue(1);
    for (int c = 0; c < 16; ++c) {
        if (c < 15) cp_wait<1>(); else cp_wait<0>();
        __syncthreads();
        if (c + 2 < 16) issue(c + 2);

        const float* Ab = sm + (c % 3) * PJ_B_F;                 // [co][k]
        const float* Bb = sm + 3 * PJ_B_F + (c % 3) * PJ_A_F;    // [k][p]

        #pragma unroll
        for (int ks = 0; ks < 4; ++ks) {
            const int col = ks * 8 + tig;
            uint32_t ah[4][4];
            #pragma unroll
            for (int mt = 0; mt < 4; ++mt) {
                int m = wm * 64 + mt * 16 + gid;
                ah[mt][0] = __float_as_uint(Ab[m * PADR + col])           & 0xFFFFE000u;
                ah[mt][1] = __float_as_uint(Ab[(m + 8) * PADR + col])     & 0xFFFFE000u;
                ah[mt][2] = __float_as_uint(Ab[m * PADR + col + 4])       & 0xFFFFE000u;
                ah[mt][3] = __float_as_uint(Ab[(m + 8) * PADR + col + 4]) & 0xFFFFE000u;
            }
            #pragma unroll
            for (int nt = 0; nt < 4; ++nt) {
                int n = wn * 32 + nt * 8 + gid;
                uint32_t bh0, bl0, bh1, bl1;
                tf32_split(Bb[col * PADK + n],       bh0, bl0);
                tf32_split(Bb[(col + 4) * PADK + n], bh1, bl1);
                #pragma unroll
                for (int mt = 0; mt < 4; ++mt) {
                    mma_tf32_16n8k8(acc[mt][nt],
                                    ah[mt][0], ah[mt][1], ah[mt][2], ah[mt][3],
                                    bh0, bh1);
                    mma_tf32_16n8k8(acc[mt][nt],
                                    ah[mt][0], ah[mt][1], ah[mt][2], ah[mt][3],
                                    bl0, bl1);
                }
            }
        }
    }

    #pragma unroll
    for (int mt = 0; mt < 4; ++mt) {
        int co = co0 + wm * 64 + mt * 16 + gid;
        float bs0 = b6[co], bs1 = b6[co + 8];
        #pragma unroll
        for (int nt = 0; nt < 4; ++nt) {
            int p = p0 + wn * 32 + nt * 8 + tig * 2;
            float g0 = g_w[b * HWD + p];
            float g1 = g_w[b * HWD + p + 1];
            float2 o0 = { acc[mt][nt][0] * g0 + bs0, acc[mt][nt][1] * g1 + bs0 };
            float2 o1 = { acc[mt][nt][2] * g0 + bs1, acc[mt][nt][3] * g1 + bs1 };
            *(float2*)&out[((size_t)(b * CC + co)) * HWD + p]     = o0;
            *(float2*)&out[((size_t)(b * CC + co + 8)) * HWD + p] = o1;
        }
    }
}

// ============================================================================
extern "C" void kernel_launch(void* const* d_in, const int* in_sizes, int n_in,
                              void* d_out, int out_size)
{
    const float* x  = (const float*)d_in[0];
    const float* Wq = (const float*)d_in[1];
    const float* bq = (const float*)d_in[2];
    const float* Wk = (const float*)d_in[3];
    const float* bk = (const float*)d_in[4];
    const float* W6 = (const float*)d_in[5];
    const float* b6 = (const float*)d_in[6];
    float* out = (float*)d_out;

    cudaFuncSetAttribute(projb_kernel,
                         cudaFuncAttributeMaxDynamicSharedMemorySize, PJ4_SMEM);
    cudaFuncSetAttribute(scores_mma_kernel,
                         cudaFuncAttributeMaxDynamicSharedMemorySize, SC3_SMEM);
    cudaFuncSetAttribute(outconv_tc_kernel,
                         cudaFuncAttributeMaxDynamicSharedMemorySize, PJ_SMEM);

    dim3 blk(256);
    wconv_kernel<<<dim3(512, 2), blk>>>(Wq, Wk);
    xpose_kernel<<<dim3(32, 16, 8), blk>>>(x);
    projb_kernel<<<dim3(64, 4, 2), blk, PJ4_SMEM>>>(bq, bk);
    scores_mma_kernel<<<GRID_SC, blk, SC3_SMEM>>>();
    softmax_kernel<<<BB, blk>>>();
    outconv_tc_kernel<<<dim3(CC / 128, HWD / 128, BB), blk, PJ_SMEM>>>(x, W6, b6, out);
}